// round 10
// baseline (speedup 1.0000x reference)
#include <cuda_runtime.h>

// Aggre_81226421502275: y[n] = mean_k( relu(mailbox[n,k,:]@W1 + b1) @ W2 + b2 )
// N=500000, K=16, F_IN=7, F_HID=40, F_OUT=3. All fp32.
//
// R10: register-pressure fix. R9 spilled (255 regs, occ 11.3%, L1 64.6% = LDL/STL).
//  - k-tile 4 -> 2: broadcast msg tile 56 -> 28 regs
//  - float2 tile loads (no scalar staging regs)
//  - __launch_bounds__(128, 4): cap 128 regs -> 4 CTAs/SM (50% occ)
// Math unchanged: mean hoisted out of layer 2; FFMA2 (fma.rn.f32x2) for layer 1.

#define KK    16
#define FIN   7
#define FHID  40
#define FOUT  3
#define KT    2            // messages per k-tile
#define NT    (KK / KT)    // 8 tiles
#define JP    (FHID / 2)   // 20 hidden pairs
#define TPB   128

__device__ __forceinline__ unsigned long long bcast2(float x) {
    unsigned long long r;
    asm("mov.b64 %0, {%1, %1};" : "=l"(r) : "f"(x));
    return r;
}
__device__ __forceinline__ unsigned long long pack2(float x, float y) {
    unsigned long long r;
    asm("mov.b64 %0, {%1, %2};" : "=l"(r) : "f"(x), "f"(y));
    return r;
}
__device__ __forceinline__ void unpack2(unsigned long long v, float &x, float &y) {
    asm("mov.b64 {%0, %1}, %2;" : "=f"(x), "=f"(y) : "l"(v));
}
__device__ __forceinline__ unsigned long long fma2(unsigned long long a,
                                                   unsigned long long b,
                                                   unsigned long long c) {
    unsigned long long d;
    asm("fma.rn.f32x2 %0, %1, %2, %3;" : "=l"(d) : "l"(a), "l"(b), "l"(c));
    return d;
}

__global__ __launch_bounds__(TPB, 4)
void aggre_mlp_kernel(const float* __restrict__ mailbox,
                      const float* __restrict__ W1,
                      const float* __restrict__ b1,
                      const float* __restrict__ W2,
                      const float* __restrict__ b2,
                      float* __restrict__ out,
                      int N)
{
    // Packed weights in shared memory (warp-broadcast LDS.64, conflict-free).
    __shared__ unsigned long long sW1p[FIN * JP];   // [f][jp] = pair (W1[f][2jp], W1[f][2jp+1])
    __shared__ unsigned long long sb1p[JP];
    __shared__ float              sW2[FHID * FOUT]; // row-major [j][o]
    __shared__ float              sb2[FOUT];

    const int tid = threadIdx.x;
    for (int i = tid; i < FIN * JP; i += TPB) sW1p[i] = pack2(W1[2 * i], W1[2 * i + 1]);
    for (int i = tid; i < JP;       i += TPB) sb1p[i] = pack2(b1[2 * i], b1[2 * i + 1]);
    for (int i = tid; i < FHID * FOUT; i += TPB) sW2[i] = W2[i];
    if (tid < FOUT) sb2[tid] = b2[tid];
    __syncthreads();

    const int n = blockIdx.x * TPB + tid;
    if (n >= N) return;

    float hsum[FHID];
#pragma unroll
    for (int j = 0; j < FHID; j++) hsum[j] = 0.0f;

    // 448 B per node; 56 B per 2-message tile (8 B aligned) -> 7 float2 loads.
    const float2* mp = reinterpret_cast<const float2*>(mailbox + (long long)n * (KK * FIN));

#pragma unroll 1
    for (int t = 0; t < NT; t++) {
        // Load one k-tile (2 messages x 7 feats = 14 floats) broadcast-packed.
        unsigned long long mb[KT * FIN];   // 14 u64 = 28 regs
#pragma unroll
        for (int i = 0; i < (KT * FIN) / 2; i++) {
            float2 vv = mp[t * ((KT * FIN) / 2) + i];
            mb[2 * i + 0] = bcast2(vv.x);
            mb[2 * i + 1] = bcast2(vv.y);
        }

#pragma unroll
        for (int jp = 0; jp < JP; jp++) {
            unsigned long long w[FIN];
#pragma unroll
            for (int f = 0; f < FIN; f++) w[f] = sW1p[f * JP + jp];
            const unsigned long long bb = sb1p[jp];

#pragma unroll
            for (int kk = 0; kk < KT; kk++) {
                unsigned long long acc = bb;
#pragma unroll
                for (int f = 0; f < FIN; f++)
                    acc = fma2(mb[kk * FIN + f], w[f], acc);
                float ax, ay;
                unpack2(acc, ax, ay);
                hsum[2 * jp]     += fmaxf(ax, 0.0f);
                hsum[2 * jp + 1] += fmaxf(ay, 0.0f);
            }
        }
    }

    // Layer 2 on the k-summed hidden vector: y = hsum @ W2 / K + b2.
    float y0 = 0.0f, y1 = 0.0f, y2 = 0.0f;
#pragma unroll
    for (int j = 0; j < FHID; j++) {
        const float h = hsum[j];
        y0 = fmaf(h, sW2[j * FOUT + 0], y0);
        y1 = fmaf(h, sW2[j * FOUT + 1], y1);
        y2 = fmaf(h, sW2[j * FOUT + 2], y2);
    }
    const float inv = 1.0f / (float)KK;
    out[n * FOUT + 0] = fmaf(y0, inv, sb2[0]);
    out[n * FOUT + 1] = fmaf(y1, inv, sb2[1]);
    out[n * FOUT + 2] = fmaf(y2, inv, sb2[2]);
}

extern "C" void kernel_launch(void* const* d_in, const int* in_sizes, int n_in,
                              void* d_out, int out_size)
{
    const float* mailbox = (const float*)d_in[0];
    const float* W1      = (const float*)d_in[1];
    const float* b1      = (const float*)d_in[2];
    const float* W2      = (const float*)d_in[3];
    const float* b2      = (const float*)d_in[4];
    float*       out     = (float*)d_out;

    const int N = in_sizes[0] / (KK * FIN);
    const int blocks = (N + TPB - 1) / TPB;
    aggre_mlp_kernel<<<blocks, TPB>>>(mailbox, W1, b1, W2, b2, out, N);
}

// round 11
// speedup vs baseline: 3.5893x; 3.5893x over previous
#include <cuda_runtime.h>

// Aggre_81226421502275: y[n] = mean_k( relu(mailbox[n,k,:]@W1 + b1) @ W2 + b2 )
// N=500000, K=16, F_IN=7, F_HID=40, F_OUT=3. fp32.
//
// R11: structural register-pressure fix (R9/R10 spilled).
//  - 2 threads per node, each owns 20 of 40 hidden units -> packed accum = 10 u64 (20 regs)
//  - pair lanes read identical addresses -> HW broadcast, DRAM stays 224 MB
//  - FFMA2 (fma.rn.f32x2) hidden-pair packing; relu via sign-mask (stays packed);
//    packed add.rn.f32x2 accumulate; W1/b1 packed pairs in shared
//  - layer-2 partials combined with shfl_xor(1); no forced occupancy cap

#define KK    16
#define FIN   7
#define FHID  40
#define FOUT  3
#define JP    20          // hidden pairs total
#define JPT   10          // hidden pairs per thread (2-way split)
#define TPB   128

typedef unsigned long long u64;
typedef unsigned int       u32;

__device__ __forceinline__ u64 bcast2(float x) {
    u64 r; asm("mov.b64 %0, {%1, %1};" : "=l"(r) : "f"(x)); return r;
}
__device__ __forceinline__ u64 pack2(float x, float y) {
    u64 r; asm("mov.b64 %0, {%1, %2};" : "=l"(r) : "f"(x), "f"(y)); return r;
}
__device__ __forceinline__ void unpack2(u64 v, float &x, float &y) {
    asm("mov.b64 {%0, %1}, %2;" : "=f"(x), "=f"(y) : "l"(v));
}
__device__ __forceinline__ u64 fma2(u64 a, u64 b, u64 c) {
    u64 d; asm("fma.rn.f32x2 %0, %1, %2, %3;" : "=l"(d) : "l"(a), "l"(b), "l"(c)); return d;
}
__device__ __forceinline__ u64 add2(u64 a, u64 b) {
    u64 d; asm("add.rn.f32x2 %0, %1, %2;" : "=l"(d) : "l"(a), "l"(b)); return d;
}
// relu on both packed fp32 halves: zero the half if its sign bit is set.
// (alu pipe: SHF + LOP3 per half; no unpack/repack float movs, stays packed)
__device__ __forceinline__ u64 relu2(u64 v) {
    u32 lo, hi;
    asm("mov.b64 {%0, %1}, %2;" : "=r"(lo), "=r"(hi) : "l"(v));
    lo &= ~(u32)((int)lo >> 31);
    hi &= ~(u32)((int)hi >> 31);
    u64 r; asm("mov.b64 %0, {%1, %2};" : "=l"(r) : "r"(lo), "r"(hi));
    return r;
}

__global__ __launch_bounds__(TPB)
void aggre_mlp_kernel(const float* __restrict__ mailbox,
                      const float* __restrict__ W1,
                      const float* __restrict__ b1,
                      const float* __restrict__ W2,
                      const float* __restrict__ b2,
                      float* __restrict__ out,
                      int N)
{
    // Packed weights in shared (LDS.64; at most 2 distinct addrs/warp, conflict-free).
    __shared__ u64   sW1p[FIN * JP];   // [f][jp] = (W1[f][2jp], W1[f][2jp+1])
    __shared__ u64   sb1p[JP];
    __shared__ float sW2[FHID * FOUT]; // row-major [j][o]
    __shared__ float sb2[FOUT];

    const int tid = threadIdx.x;
    for (int i = tid; i < FIN * JP; i += TPB) sW1p[i] = pack2(W1[2 * i], W1[2 * i + 1]);
    for (int i = tid; i < JP;       i += TPB) sb1p[i] = pack2(b1[2 * i], b1[2 * i + 1]);
    for (int i = tid; i < FHID * FOUT; i += TPB) sW2[i] = W2[i];
    if (tid < FOUT) sb2[tid] = b2[tid];
    __syncthreads();

    const int gt    = blockIdx.x * TPB + tid;
    const int n     = gt >> 1;        // node
    const int jh    = gt & 1;         // hidden half (0: j 0..19, 1: j 20..39)
    const bool live = (n < N);
    const int nc    = live ? n : (N - 1);   // clamp so exited-lane-free warp for shfl
    const int jb    = jh * JPT;

    u64 hs[JPT];                      // packed hidden-pair accumulators (sum over k)
#pragma unroll
    for (int i = 0; i < JPT; i++) hs[i] = 0ull;

    // 448 B per node; per 2-message tile: 14 consecutive floats (8 B aligned).
    const float2* mp = reinterpret_cast<const float2*>(mailbox + (long long)nc * (KK * FIN));

#pragma unroll 1
    for (int t = 0; t < KK / 2; t++) {
        // Load 2 messages (14 floats), broadcast-pack per feature.
        float a[2 * FIN];
#pragma unroll
        for (int i = 0; i < FIN; i++) {
            float2 v = mp[t * FIN + i];
            a[2 * i]     = v.x;
            a[2 * i + 1] = v.y;
        }
        u64 m0[FIN], m1[FIN];
#pragma unroll
        for (int f = 0; f < FIN; f++) {
            m0[f] = bcast2(a[f]);
            m1[f] = bcast2(a[FIN + f]);
        }

#pragma unroll 2
        for (int jp = 0; jp < JPT; jp++) {
            const int j = jb + jp;
            const u64 bb = sb1p[j];
            u64 acc0 = bb, acc1 = bb;
#pragma unroll
            for (int f = 0; f < FIN; f++) {
                const u64 w = sW1p[f * JP + j];
                acc0 = fma2(m0[f], w, acc0);
                acc1 = fma2(m1[f], w, acc1);
            }
            hs[jp] = add2(hs[jp], add2(relu2(acc0), relu2(acc1)));
        }
    }

    // Layer 2 on this thread's half of the hidden vector.
    float y0 = 0.0f, y1 = 0.0f, y2 = 0.0f;
#pragma unroll
    for (int jp = 0; jp < JPT; jp++) {
        const int j2 = 2 * (jb + jp);
        float h0, h1;
        unpack2(hs[jp], h0, h1);
        y0 = fmaf(h0, sW2[j2 * FOUT + 0], y0);
        y1 = fmaf(h0, sW2[j2 * FOUT + 1], y1);
        y2 = fmaf(h0, sW2[j2 * FOUT + 2], y2);
        y0 = fmaf(h1, sW2[(j2 + 1) * FOUT + 0], y0);
        y1 = fmaf(h1, sW2[(j2 + 1) * FOUT + 1], y1);
        y2 = fmaf(h1, sW2[(j2 + 1) * FOUT + 2], y2);
    }

    // Combine the two hidden halves across the lane pair.
    y0 += __shfl_xor_sync(0xffffffffu, y0, 1);
    y1 += __shfl_xor_sync(0xffffffffu, y1, 1);
    y2 += __shfl_xor_sync(0xffffffffu, y2, 1);

    if (live && jh == 0) {
        const float inv = 1.0f / (float)KK;
        out[n * FOUT + 0] = fmaf(y0, inv, sb2[0]);
        out[n * FOUT + 1] = fmaf(y1, inv, sb2[1]);
        out[n * FOUT + 2] = fmaf(y2, inv, sb2[2]);
    }
}

extern "C" void kernel_launch(void* const* d_in, const int* in_sizes, int n_in,
                              void* d_out, int out_size)
{
    const float* mailbox = (const float*)d_in[0];
    const float* W1      = (const float*)d_in[1];
    const float* b1      = (const float*)d_in[2];
    const float* W2      = (const float*)d_in[3];
    const float* b2      = (const float*)d_in[4];
    float*       out     = (float*)d_out;

    const int N = in_sizes[0] / (KK * FIN);
    const long long threads = 2LL * N;
    const int blocks = (int)((threads + TPB - 1) / TPB);
    aggre_mlp_kernel<<<blocks, TPB>>>(mailbox, W1, b1, W2, b2, out, N);
}

// round 12
// speedup vs baseline: 6.6971x; 1.8659x over previous
#include <cuda_runtime.h>

// Aggre_81226421502275: y[n] = mean_k( relu(mailbox[n,k,:]@W1 + b1) @ W2 + b2 )
// N=500000, K=16, F_IN=7, F_HID=40, F_OUT=3. fp32.
//
// R12: kill the L1tex wavefront waste found in R11 (L1=93.9%, 16x LDG wf waste).
//  - block stages 64 nodes (28 KB) into shared via coalesced float4 LDG
//    (4 wf/warp-LDG = HW minimum vs 16 wf before)
//  - shared mailbox row stride = 118 floats -> conflict-free pair-broadcast LDS.64
//  - W1/b1 as 16B quads (two hidden pairs) in shared -> LDS.128, halves W-LDS count
//  - unchanged: 2 threads/node (hidden split 20/20), FFMA2, packed relu/add, shfl combine

#define KK    16
#define FIN   7
#define FHID  40
#define FOUT  3
#define NPB   64            // nodes per block
#define TPB   128
#define ROWS  118           // padded smem row stride (floats): 22p mod 32 distinct for 16 pairs
#define NQ    10            // weight quads along hidden (40/4)
#define JQT   5             // quads per thread (half of hidden)

typedef unsigned long long u64;
typedef unsigned int       u32;

__device__ __forceinline__ u64 bcast2(float x) {
    u64 r; asm("mov.b64 %0, {%1, %1};" : "=l"(r) : "f"(x)); return r;
}
__device__ __forceinline__ u64 pack2(float x, float y) {
    u64 r; asm("mov.b64 %0, {%1, %2};" : "=l"(r) : "f"(x), "f"(y)); return r;
}
__device__ __forceinline__ void unpack2(u64 v, float &x, float &y) {
    asm("mov.b64 {%0, %1}, %2;" : "=f"(x), "=f"(y) : "l"(v));
}
__device__ __forceinline__ u64 fma2(u64 a, u64 b, u64 c) {
    u64 d; asm("fma.rn.f32x2 %0, %1, %2, %3;" : "=l"(d) : "l"(a), "l"(b), "l"(c)); return d;
}
__device__ __forceinline__ u64 add2(u64 a, u64 b) {
    u64 d; asm("add.rn.f32x2 %0, %1, %2;" : "=l"(d) : "l"(a), "l"(b)); return d;
}
// packed relu: zero each fp32 half whose sign bit is set (alu pipe)
__device__ __forceinline__ u64 relu2(u64 v) {
    u32 lo, hi;
    asm("mov.b64 {%0, %1}, %2;" : "=r"(lo), "=r"(hi) : "l"(v));
    lo &= ~(u32)((int)lo >> 31);
    hi &= ~(u32)((int)hi >> 31);
    u64 r; asm("mov.b64 %0, {%1, %2};" : "=l"(r) : "r"(lo), "r"(hi));
    return r;
}

__global__ __launch_bounds__(TPB)
void aggre_mlp_kernel(const float* __restrict__ mailbox,
                      const float* __restrict__ W1,
                      const float* __restrict__ b1,
                      const float* __restrict__ W2,
                      const float* __restrict__ b2,
                      float* __restrict__ out,
                      int N)
{
    __shared__ float      smb[NPB * ROWS];      // staged mailbox, padded rows
    __shared__ ulonglong2 sW1q[FIN * NQ];       // [f][jq]: .x=pair(4jq,4jq+1) .y=pair(4jq+2,4jq+3)
    __shared__ ulonglong2 sb1q[NQ];
    __shared__ float      sW2[FHID * FOUT];     // row-major [j][o]
    __shared__ float      sb2[FOUT];

    const int tid = threadIdx.x;

    // ---- weight prep ----
    for (int i = tid; i < FIN * NQ; i += TPB) {
        const int f = i / NQ, jq = i % NQ;
        const float* w = W1 + f * FHID + 4 * jq;
        ulonglong2 q;
        q.x = pack2(w[0], w[1]);
        q.y = pack2(w[2], w[3]);
        sW1q[i] = q;
    }
    if (tid < NQ) {
        const float* bp = b1 + 4 * tid;
        ulonglong2 q;
        q.x = pack2(bp[0], bp[1]);
        q.y = pack2(bp[2], bp[3]);
        sb1q[tid] = q;
    }
    for (int i = tid; i < FHID * FOUT; i += TPB) sW2[i] = W2[i];
    if (tid < FOUT) sb2[tid] = b2[tid];

    // ---- stage mailbox: 64 nodes x 112 floats = 1792 float4, coalesced ----
    const int node0 = blockIdx.x * NPB;
    const int valid = min(NPB, N - node0);                 // >=1 by grid sizing
    const int vq    = valid * (KK * FIN / 4);              // valid float4 count
    const float4* gsrc = reinterpret_cast<const float4*>(mailbox + (long long)node0 * (KK * FIN));
#pragma unroll
    for (int i = 0; i < (NPB * KK * FIN / 4) / TPB; i++) { // 14 iterations
        int idx = i * TPB + tid;
        if (idx >= vq) idx = vq - 1;                       // clamp (benign dup stores)
        const float4 v = gsrc[idx];
        const int fidx = idx * 4;
        const int node = fidx / (KK * FIN);
        const int off  = fidx - node * (KK * FIN);
        float* d = &smb[node * ROWS + off];
        d[0] = v.x; d[1] = v.y; d[2] = v.z; d[3] = v.w;
    }
    __syncthreads();

    // ---- compute: 2 threads per node, each owns 20 hidden units (5 quads) ----
    const int nl   = tid >> 1;                 // local node 0..63
    const int jh   = tid & 1;                  // hidden half
    const int n    = node0 + nl;
    const bool live = (n < N);
    const int nlc  = live ? nl : 0;
    const int jqb  = jh * JQT;

    u64 hs[2 * JQT];                           // 10 packed hidden-pair accumulators
#pragma unroll
    for (int i = 0; i < 2 * JQT; i++) hs[i] = 0ull;

    const float2* mrow = reinterpret_cast<const float2*>(&smb[nlc * ROWS]);

#pragma unroll 1
    for (int t = 0; t < KK / 2; t++) {
        // 2 messages (14 floats) from shared, broadcast-packed
        u64 m0[FIN], m1[FIN];
#pragma unroll
        for (int i = 0; i < FIN; i++) {
            const float2 v = mrow[t * FIN + i];
            if (i & 1) { m0[i] = bcast2(v.x); }           // pattern irrelevant; see below
            m0[i] = bcast2(0.0f); m1[i] = bcast2(0.0f);   // placeholder overwritten
        }
        // (clean re-load: features are interleaved msg0,msg1 pairs? No — layout is
        //  msg0[0..6], msg1[0..6]; re-read properly:)
        {
            float a[2 * FIN];
#pragma unroll
            for (int i = 0; i < FIN; i++) {
                const float2 v = mrow[t * FIN + i];
                a[2 * i] = v.x; a[2 * i + 1] = v.y;
            }
#pragma unroll
            for (int f = 0; f < FIN; f++) {
                m0[f] = bcast2(a[f]);
                m1[f] = bcast2(a[FIN + f]);
            }
        }

#pragma unroll
        for (int jq = 0; jq < JQT; jq++) {
            const ulonglong2 bq = sb1q[jqb + jq];
            u64 a0x = bq.x, a0y = bq.y, a1x = bq.x, a1y = bq.y;
#pragma unroll
            for (int f = 0; f < FIN; f++) {
                const ulonglong2 wq = sW1q[f * NQ + jqb + jq];
                a0x = fma2(m0[f], wq.x, a0x);
                a0y = fma2(m0[f], wq.y, a0y);
                a1x = fma2(m1[f], wq.x, a1x);
                a1y = fma2(m1[f], wq.y, a1y);
            }
            hs[2 * jq]     = add2(hs[2 * jq],     add2(relu2(a0x), relu2(a1x)));
            hs[2 * jq + 1] = add2(hs[2 * jq + 1], add2(relu2(a0y), relu2(a1y)));
        }
    }

    // ---- layer 2 on this thread's hidden half, then pair-combine ----
    float y0 = 0.0f, y1 = 0.0f, y2 = 0.0f;
#pragma unroll
    for (int p = 0; p < 2 * JQT; p++) {
        const int j2 = 2 * (jh * FHID / 2 / 2 * 2 + 0) + 0; // (computed below properly)
        (void)j2;
        const int j = jh * (FHID / 2) + 2 * p;              // hidden index of pair p, lo half
        float h0, h1;
        unpack2(hs[p], h0, h1);
        y0 = fmaf(h0, sW2[j * FOUT + 0], y0);
        y1 = fmaf(h0, sW2[j * FOUT + 1], y1);
        y2 = fmaf(h0, sW2[j * FOUT + 2], y2);
        y0 = fmaf(h1, sW2[(j + 1) * FOUT + 0], y0);
        y1 = fmaf(h1, sW2[(j + 1) * FOUT + 1], y1);
        y2 = fmaf(h1, sW2[(j + 1) * FOUT + 2], y2);
    }

    y0 += __shfl_xor_sync(0xffffffffu, y0, 1);
    y1 += __shfl_xor_sync(0xffffffffu, y1, 1);
    y2 += __shfl_xor_sync(0xffffffffu, y2, 1);

    if (live && jh == 0) {
        const float inv = 1.0f / (float)KK;
        out[n * FOUT + 0] = fmaf(y0, inv, sb2[0]);
        out[n * FOUT + 1] = fmaf(y1, inv, sb2[1]);
        out[n * FOUT + 2] = fmaf(y2, inv, sb2[2]);
    }
}

extern "C" void kernel_launch(void* const* d_in, const int* in_sizes, int n_in,
                              void* d_out, int out_size)
{
    const float* mailbox = (const float*)d_in[0];
    const float* W1      = (const float*)d_in[1];
    const float* b1      = (const float*)d_in[2];
    const float* W2      = (const float*)d_in[3];
    const float* b2      = (const float*)d_in[4];
    float*       out     = (float*)d_out;

    const int N = in_sizes[0] / (KK * FIN);
    const int blocks = (N + NPB - 1) / NPB;
    aggre_mlp_kernel<<<blocks, TPB>>>(mailbox, W1, b1, W2, b2, out, N);
}